// round 3
// baseline (speedup 1.0000x reference)
#include <cuda_runtime.h>
#include <cuda_bf16.h>
#include <cstdint>

#define PRIME1 2654435761u
#define PRIME2 805459861u
#define HMASK  0x7FFFFu

#define TPB 256
// Row pitch 36 floats: multiple of 4 (16B-aligned float4 reads) and the
// 8-thread LDS.128 phases each read one full 32-float row -> conflict-free.
#define PITCH 36

__global__ void __launch_bounds__(TPB)
grid_encode_kernel(const float* __restrict__ inp,
                   const float2* __restrict__ emb,    // level 0 (4920 rows)
                   const float2* __restrict__ tab,    // levels 1..15
                   const int* __restrict__ boundp,
                   float* __restrict__ out,
                   int B)
{
    __shared__ float s_out[TPB * PITCH];

    const int tid = threadIdx.x;
    const long long b = (long long)blockIdx.x * TPB + tid;
    const bool valid = (b < B);

    // bound: dataset always has bound=1 (python int). Read robustly whether it
    // was serialized as int32 or float32.
    float bnd = 1.0f;
    if (boundp) {
        int raw = __ldg(boundp);
        bnd = (raw > 0 && raw < 0x00800000) ? (float)raw : __int_as_float(raw);
    }
    const float inv = 0.5f / bnd;

    float x = 0.f, y = 0.f, z = 0.f;
    if (valid) {
        const float* p = inp + b * 3;
        x = __ldg(p + 0); y = __ldg(p + 1); z = __ldg(p + 2);
    }
    // x01 = (x + bound) / (2*bound) = x * (0.5/bound) + 0.5
    x = fmaf(x, inv, 0.5f);
    y = fmaf(y, inv, 0.5f);
    z = fmaf(z, inv, 0.5f);

    if (valid) {
#pragma unroll
        for (int l = 0; l < 16; l++) {
            const float scale = (float)(16 << l) - 1.0f;
            const float px = fmaf(x, scale, 0.5f);
            const float py = fmaf(y, scale, 0.5f);
            const float pz = fmaf(z, scale, 0.5f);
            const float fxf = floorf(px), fyf = floorf(py), fzf = floorf(pz);
            const float fx = px - fxf, fy = py - fyf, fz = pz - fzf;
            const unsigned ix = (unsigned)fxf, iy = (unsigned)fyf, iz = (unsigned)fzf;
            const float gx = 1.0f - fx, gy = 1.0f - fy, gz = 1.0f - fz;

            // x-y weight combos, reused across the two z planes
            const float w00 = gx * gy, w10 = fx * gy, w01 = gx * fy, w11 = fx * fy;

            unsigned i0, i1, i2, i3, i4, i5, i6, i7;
            const float2* base;
            if (l == 0) {
                // dense, s = 17, lives in `embeddings`
                const unsigned s = 17u, s2 = 17u * 17u;
                const unsigned id = ix + iy * s + iz * s2;
                base = emb;
                i0 = id;      i1 = id + 1;      i2 = id + s;      i3 = id + s + 1;
                i4 = id + s2; i5 = id + s2 + 1; i6 = id + s2 + s; i7 = id + s2 + s + 1;
            } else if (l <= 2) {
                // dense, s = 33 / 65, table offset OFFSETS[l]-4920
                const unsigned s  = (l == 1) ? 33u : 65u;
                const unsigned s2 = s * s;
                const unsigned off = (l == 1) ? 0u : 35944u;
                const unsigned id = ix + iy * s + iz * s2 + off;
                base = tab;
                i0 = id;      i1 = id + 1;      i2 = id + s;      i3 = id + s + 1;
                i4 = id + s2; i5 = id + s2 + 1; i6 = id + s2 + s; i7 = id + s2 + s + 1;
            } else {
                // hashed, hsz = 2^19 exactly -> mod is a mask
                const unsigned off = 310576u + (unsigned)(l - 3) * 524288u;
                const unsigned hx0 = ix, hx1 = ix + 1u;
                const unsigned hy0 = iy * PRIME1, hy1 = hy0 + PRIME1;
                const unsigned hz0 = iz * PRIME2, hz1 = hz0 + PRIME2;
                base = tab;
                i0 = ((hx0 ^ hy0 ^ hz0) & HMASK) + off;
                i1 = ((hx1 ^ hy0 ^ hz0) & HMASK) + off;
                i2 = ((hx0 ^ hy1 ^ hz0) & HMASK) + off;
                i3 = ((hx1 ^ hy1 ^ hz0) & HMASK) + off;
                i4 = ((hx0 ^ hy0 ^ hz1) & HMASK) + off;
                i5 = ((hx1 ^ hy0 ^ hz1) & HMASK) + off;
                i6 = ((hx0 ^ hy1 ^ hz1) & HMASK) + off;
                i7 = ((hx1 ^ hy1 ^ hz1) & HMASK) + off;
            }

            // Issue all 8 gathers before consuming (MLP = 8)
            const float2 e0 = __ldg(base + i0);
            const float2 e1 = __ldg(base + i1);
            const float2 e2 = __ldg(base + i2);
            const float2 e3 = __ldg(base + i3);
            const float2 e4 = __ldg(base + i4);
            const float2 e5 = __ldg(base + i5);
            const float2 e6 = __ldg(base + i6);
            const float2 e7 = __ldg(base + i7);

            const float wa = w00 * gz, wb = w10 * gz, wc = w01 * gz, wd = w11 * gz;
            const float we = w00 * fz, wf = w10 * fz, wg = w01 * fz, wh = w11 * fz;

            float r0 = wa * e0.x,            r1 = wa * e0.y;
            r0 = fmaf(wb, e1.x, r0);         r1 = fmaf(wb, e1.y, r1);
            r0 = fmaf(wc, e2.x, r0);         r1 = fmaf(wc, e2.y, r1);
            r0 = fmaf(wd, e3.x, r0);         r1 = fmaf(wd, e3.y, r1);
            r0 = fmaf(we, e4.x, r0);         r1 = fmaf(we, e4.y, r1);
            r0 = fmaf(wf, e5.x, r0);         r1 = fmaf(wf, e5.y, r1);
            r0 = fmaf(wg, e6.x, r0);         r1 = fmaf(wg, e6.y, r1);
            r0 = fmaf(wh, e7.x, r0);         r1 = fmaf(wh, e7.y, r1);

            // float2 store (8B-aligned: tid*36 + 2l is even)
            *(float2*)&s_out[tid * PITCH + 2 * l] = make_float2(r0, r1);
        }
    }

    __syncthreads();

    // Coalesced float4 writeback with .cs (evict-first) so the 256MB output
    // stream doesn't flush the 57MB table out of L2.
    const long long blockBase = (long long)blockIdx.x * (TPB * 32);
#pragma unroll
    for (int j = 0; j < 8; j++) {
        const int f4 = tid + j * TPB;     // float4 index within block, 0..2047
        const int fl = f4 * 4;            // float index within block
        const int p  = fl >> 5;           // point-in-block
        const int k  = fl & 31;           // channel offset (multiple of 4)
        const long long gp = (long long)blockIdx.x * TPB + p;
        if (gp < B) {
            const float4 v = *(const float4*)&s_out[p * PITCH + k];
            __stcs((float4*)&out[blockBase + fl], v);
        }
    }
}

extern "C" void kernel_launch(void* const* d_in, const int* in_sizes, int n_in,
                              void* d_out, int out_size)
{
    const float*  inp = (const float*)d_in[0];
    const float2* emb = (const float2*)d_in[1];
    const float2* tab = (const float2*)d_in[2];
    const int*    bnd = (n_in >= 4) ? (const int*)d_in[3] : nullptr;
    float* out = (float*)d_out;

    const int B = in_sizes[0] / 3;
    const int grid = (B + TPB - 1) / TPB;
    grid_encode_kernel<<<grid, TPB>>>(inp, emb, tab, bnd, out, B);
}

// round 4
// speedup vs baseline: 1.0286x; 1.0286x over previous
#include <cuda_runtime.h>
#include <cuda_bf16.h>
#include <cstdint>

#define PRIME1 2654435761u
#define PRIME2 805459861u
#define HMASK  0x7FFFFu

#define TPB 256
// Row pitch 36 floats: multiple of 4 (16B-aligned float4 reads) and the
// 8-thread LDS.128 phases each read one full 32-float row -> conflict-free.
#define PITCH 36

__global__ void __launch_bounds__(TPB)
grid_encode_kernel(const float* __restrict__ inp,
                   const float2* __restrict__ emb,    // level 0 (4920 rows)
                   const float2* __restrict__ tab,    // levels 1..15
                   const int* __restrict__ boundp,
                   float* __restrict__ out,
                   int B)
{
    __shared__ float s_out[TPB * PITCH];

    const int tid = threadIdx.x;
    const long long b = (long long)blockIdx.x * TPB + tid;
    const bool valid = (b < B);

    // bound: dataset always has bound=1 (python int). Read robustly whether it
    // was serialized as int32 or float32.
    float bnd = 1.0f;
    if (boundp) {
        int raw = __ldg(boundp);
        bnd = (raw > 0 && raw < 0x00800000) ? (float)raw : __int_as_float(raw);
    }
    const float inv = 0.5f / bnd;

    float x = 0.f, y = 0.f, z = 0.f;
    if (valid) {
        const float* p = inp + b * 3;
        x = __ldcs(p + 0); y = __ldcs(p + 1); z = __ldcs(p + 2);
    }
    // x01 = (x + bound) / (2*bound) = x * (0.5/bound) + 0.5
    x = fmaf(x, inv, 0.5f);
    y = fmaf(y, inv, 0.5f);
    z = fmaf(z, inv, 0.5f);

    if (valid) {
#pragma unroll
        for (int l = 0; l < 16; l++) {
            const float scale = (float)(16 << l) - 1.0f;
            const float px = fmaf(x, scale, 0.5f);
            const float py = fmaf(y, scale, 0.5f);
            const float pz = fmaf(z, scale, 0.5f);
            const float fxf = floorf(px), fyf = floorf(py), fzf = floorf(pz);
            const float fx = px - fxf, fy = py - fyf, fz = pz - fzf;
            const unsigned ix = (unsigned)fxf, iy = (unsigned)fyf, iz = (unsigned)fzf;
            const float gx = 1.0f - fx, gy = 1.0f - fy, gz = 1.0f - fz;

            // x-y weight combos, reused across the two z planes
            const float w00 = gx * gy, w10 = fx * gy, w01 = gx * fy, w11 = fx * fy;

            float2 e0, e1, e2, e3, e4, e5, e6, e7;
            if (l <= 2) {
                // dense levels: small tables with real L1 reuse -> .ca (default)
                unsigned s, s2, off;
                const float2* base;
                if (l == 0) { s = 17u;  s2 = 17u * 17u;  off = 0u;      base = emb; }
                else if (l == 1) { s = 33u;  s2 = 33u * 33u;  off = 0u;      base = tab; }
                else { s = 65u;  s2 = 65u * 65u;  off = 35944u; base = tab; }
                const unsigned id = ix + iy * s + iz * s2 + off;
                e0 = __ldg(base + id);
                e1 = __ldg(base + id + 1);
                e2 = __ldg(base + id + s);
                e3 = __ldg(base + id + s + 1);
                e4 = __ldg(base + id + s2);
                e5 = __ldg(base + id + s2 + 1);
                e6 = __ldg(base + id + s2 + s);
                e7 = __ldg(base + id + s2 + s + 1);
            } else {
                // hashed levels: 4MB table, ~0% L1 hit -> cache at L2 only
                // (no 128B L1 fill per miss). hsz = 2^19 exactly -> mod == mask.
                const unsigned off = 310576u + (unsigned)(l - 3) * 524288u;
                const unsigned hx0 = ix, hx1 = ix + 1u;
                const unsigned hy0 = iy * PRIME1, hy1 = hy0 + PRIME1;
                const unsigned hz0 = iz * PRIME2, hz1 = hz0 + PRIME2;
                const unsigned i0 = ((hx0 ^ hy0 ^ hz0) & HMASK) + off;
                const unsigned i1 = ((hx1 ^ hy0 ^ hz0) & HMASK) + off;
                const unsigned i2 = ((hx0 ^ hy1 ^ hz0) & HMASK) + off;
                const unsigned i3 = ((hx1 ^ hy1 ^ hz0) & HMASK) + off;
                const unsigned i4 = ((hx0 ^ hy0 ^ hz1) & HMASK) + off;
                const unsigned i5 = ((hx1 ^ hy0 ^ hz1) & HMASK) + off;
                const unsigned i6 = ((hx0 ^ hy1 ^ hz1) & HMASK) + off;
                const unsigned i7 = ((hx1 ^ hy1 ^ hz1) & HMASK) + off;
                e0 = __ldcg(tab + i0);
                e1 = __ldcg(tab + i1);
                e2 = __ldcg(tab + i2);
                e3 = __ldcg(tab + i3);
                e4 = __ldcg(tab + i4);
                e5 = __ldcg(tab + i5);
                e6 = __ldcg(tab + i6);
                e7 = __ldcg(tab + i7);
            }

            const float wa = w00 * gz, wb = w10 * gz, wc = w01 * gz, wd = w11 * gz;
            const float we = w00 * fz, wf = w10 * fz, wg = w01 * fz, wh = w11 * fz;

            float r0 = wa * e0.x,            r1 = wa * e0.y;
            r0 = fmaf(wb, e1.x, r0);         r1 = fmaf(wb, e1.y, r1);
            r0 = fmaf(wc, e2.x, r0);         r1 = fmaf(wc, e2.y, r1);
            r0 = fmaf(wd, e3.x, r0);         r1 = fmaf(wd, e3.y, r1);
            r0 = fmaf(we, e4.x, r0);         r1 = fmaf(we, e4.y, r1);
            r0 = fmaf(wf, e5.x, r0);         r1 = fmaf(wf, e5.y, r1);
            r0 = fmaf(wg, e6.x, r0);         r1 = fmaf(wg, e6.y, r1);
            r0 = fmaf(wh, e7.x, r0);         r1 = fmaf(wh, e7.y, r1);

            // float2 store (8B-aligned: tid*36 + 2l is even)
            *(float2*)&s_out[tid * PITCH + 2 * l] = make_float2(r0, r1);
        }
    }

    __syncthreads();

    // Coalesced float4 writeback with .cs (evict-first) so the 256MB output
    // stream doesn't flush the 57MB table out of L2.
    const long long blockBase = (long long)blockIdx.x * (TPB * 32);
#pragma unroll
    for (int j = 0; j < 8; j++) {
        const int f4 = tid + j * TPB;     // float4 index within block, 0..2047
        const int fl = f4 * 4;            // float index within block
        const int p  = fl >> 5;           // point-in-block
        const int k  = fl & 31;           // channel offset (multiple of 4)
        const long long gp = (long long)blockIdx.x * TPB + p;
        if (gp < B) {
            const float4 v = *(const float4*)&s_out[p * PITCH + k];
            __stcs((float4*)&out[blockBase + fl], v);
        }
    }
}

extern "C" void kernel_launch(void* const* d_in, const int* in_sizes, int n_in,
                              void* d_out, int out_size)
{
    const float*  inp = (const float*)d_in[0];
    const float2* emb = (const float2*)d_in[1];
    const float2* tab = (const float2*)d_in[2];
    const int*    bnd = (n_in >= 4) ? (const int*)d_in[3] : nullptr;
    float* out = (float*)d_out;

    const int B = in_sizes[0] / 3;
    const int grid = (B + TPB - 1) / TPB;
    grid_encode_kernel<<<grid, TPB>>>(inp, emb, tab, bnd, out, B);
}

// round 5
// speedup vs baseline: 1.2088x; 1.1751x over previous
#include <cuda_runtime.h>
#include <cuda_bf16.h>
#include <cstdint>

#define PRIME1 2654435761u
#define PRIME2 805459861u
#define HMASK  0x7FFFFu

#define TPB 256
#define PITCH 36   // mult of 4 (aligned float4 reads); 8-thread LDS.128 phases conflict-free

__global__ void __launch_bounds__(TPB)
grid_encode_kernel(const float* __restrict__ inp,
                   const float2* __restrict__ emb,    // level 0 (4920 rows)
                   const float2* __restrict__ tab,    // levels 1..15
                   const int* __restrict__ boundp,
                   float* __restrict__ out,
                   int B)
{
    __shared__ float s_out[TPB * PITCH];

    const int tid = threadIdx.x;
    const long long b = (long long)blockIdx.x * TPB + tid;
    const bool valid = (b < B);

    float bnd = 1.0f;
    if (boundp) {
        int raw = __ldg(boundp);
        bnd = (raw > 0 && raw < 0x00800000) ? (float)raw : __int_as_float(raw);
    }
    const float inv = 0.5f / bnd;

    float x = 0.f, y = 0.f, z = 0.f;
    if (valid) {
        const float* p = inp + b * 3;
        x = __ldcs(p + 0); y = __ldcs(p + 1); z = __ldcs(p + 2);
    }
    x = fmaf(x, inv, 0.5f);
    y = fmaf(y, inv, 0.5f);
    z = fmaf(z, inv, 0.5f);

    if (valid) {
        // ---- 2-stage software pipeline: level l+1's 8 gathers are issued
        // before level l's results are consumed -> ~16 loads in flight/warp.
        float cfx = 0.f, cfy = 0.f, cfz = 0.f;   // fracs for level being consumed
        float2 cur[8];

        // helper executed inline per level (constant-folded l)
        #define ISSUE_LEVEL(LVL, FX, FY, FZ, DST)                                   \
        {                                                                            \
            const float scale = (float)(16 << (LVL)) - 1.0f;                         \
            const float px = fmaf(x, scale, 0.5f);                                   \
            const float py = fmaf(y, scale, 0.5f);                                   \
            const float pz = fmaf(z, scale, 0.5f);                                   \
            const float fxf = floorf(px), fyf = floorf(py), fzf = floorf(pz);        \
            FX = px - fxf; FY = py - fyf; FZ = pz - fzf;                             \
            const unsigned ix = (unsigned)fxf, iy = (unsigned)fyf, iz = (unsigned)fzf;\
            if ((LVL) <= 2) {                                                        \
                const unsigned s  = ((LVL) == 0) ? 17u : ((LVL) == 1) ? 33u : 65u;   \
                const unsigned s2 = s * s;                                           \
                const unsigned off = ((LVL) == 2) ? 35944u : 0u;                     \
                const float2* base = ((LVL) == 0) ? emb : tab;                       \
                const unsigned id = ix + iy * s + iz * s2 + off;                     \
                DST[0] = __ldg(base + id);                                           \
                DST[1] = __ldg(base + id + 1);                                       \
                DST[2] = __ldg(base + id + s);                                       \
                DST[3] = __ldg(base + id + s + 1);                                   \
                DST[4] = __ldg(base + id + s2);                                      \
                DST[5] = __ldg(base + id + s2 + 1);                                  \
                DST[6] = __ldg(base + id + s2 + s);                                  \
                DST[7] = __ldg(base + id + s2 + s + 1);                              \
            } else {                                                                 \
                const unsigned off = 310576u + (unsigned)((LVL) - 3) * 524288u;      \
                const unsigned hy0 = iy * PRIME1, hy1 = hy0 + PRIME1;                \
                const unsigned hz0 = iz * PRIME2, hz1 = hz0 + PRIME2;                \
                DST[0] = __ldcg(tab + (((ix      ^ hy0 ^ hz0) & HMASK) + off));      \
                DST[1] = __ldcg(tab + ((((ix+1u) ^ hy0 ^ hz0) & HMASK) + off));      \
                DST[2] = __ldcg(tab + (((ix      ^ hy1 ^ hz0) & HMASK) + off));      \
                DST[3] = __ldcg(tab + ((((ix+1u) ^ hy1 ^ hz0) & HMASK) + off));      \
                DST[4] = __ldcg(tab + (((ix      ^ hy0 ^ hz1) & HMASK) + off));      \
                DST[5] = __ldcg(tab + ((((ix+1u) ^ hy0 ^ hz1) & HMASK) + off));      \
                DST[6] = __ldcg(tab + (((ix      ^ hy1 ^ hz1) & HMASK) + off));      \
                DST[7] = __ldcg(tab + ((((ix+1u) ^ hy1 ^ hz1) & HMASK) + off));      \
            }                                                                        \
        }

        // prologue: issue level 0
        ISSUE_LEVEL(0, cfx, cfy, cfz, cur)

        #pragma unroll
        for (int l = 0; l < 16; l++) {
            float nfx, nfy, nfz;
            float2 nxt[8];
            if (l < 15) {
                // issue next level's gathers BEFORE consuming current level
                #pragma unroll
                for (int u = 0; u < 1; u++) { ISSUE_LEVEL(l + 1, nfx, nfy, nfz, nxt) }
            }

            // consume current level
            const float gx = 1.0f - cfx, gy = 1.0f - cfy, gz = 1.0f - cfz;
            const float w00 = gx * gy, w10 = cfx * gy, w01 = gx * cfy, w11 = cfx * cfy;
            const float wa = w00 * gz, wb = w10 * gz, wc = w01 * gz, wd = w11 * gz;
            const float we = w00 * cfz, wf = w10 * cfz, wg = w01 * cfz, wh = w11 * cfz;

            float r0 = wa * cur[0].x,          r1 = wa * cur[0].y;
            r0 = fmaf(wb, cur[1].x, r0);       r1 = fmaf(wb, cur[1].y, r1);
            r0 = fmaf(wc, cur[2].x, r0);       r1 = fmaf(wc, cur[2].y, r1);
            r0 = fmaf(wd, cur[3].x, r0);       r1 = fmaf(wd, cur[3].y, r1);
            r0 = fmaf(we, cur[4].x, r0);       r1 = fmaf(we, cur[4].y, r1);
            r0 = fmaf(wf, cur[5].x, r0);       r1 = fmaf(wf, cur[5].y, r1);
            r0 = fmaf(wg, cur[6].x, r0);       r1 = fmaf(wg, cur[6].y, r1);
            r0 = fmaf(wh, cur[7].x, r0);       r1 = fmaf(wh, cur[7].y, r1);

            *(float2*)&s_out[tid * PITCH + 2 * l] = make_float2(r0, r1);

            if (l < 15) {
                cfx = nfx; cfy = nfy; cfz = nfz;
                #pragma unroll
                for (int c = 0; c < 8; c++) cur[c] = nxt[c];
            }
        }
        #undef ISSUE_LEVEL
    }

    __syncthreads();

    // Coalesced float4 writeback, evict-first so the 256MB output stream
    // doesn't flush the 57MB table out of L2.
    const long long blockBase = (long long)blockIdx.x * (TPB * 32);
#pragma unroll
    for (int j = 0; j < 8; j++) {
        const int f4 = tid + j * TPB;
        const int fl = f4 * 4;
        const int p  = fl >> 5;
        const int k  = fl & 31;
        const long long gp = (long long)blockIdx.x * TPB + p;
        if (gp < B) {
            const float4 v = *(const float4*)&s_out[p * PITCH + k];
            __stcs((float4*)&out[blockBase + fl], v);
        }
    }
}

extern "C" void kernel_launch(void* const* d_in, const int* in_sizes, int n_in,
                              void* d_out, int out_size)
{
    const float*  inp = (const float*)d_in[0];
    const float2* emb = (const float2*)d_in[1];
    const float2* tab = (const float2*)d_in[2];
    const int*    bnd = (n_in >= 4) ? (const int*)d_in[3] : nullptr;
    float* out = (float*)d_out;

    const int B = in_sizes[0] / 3;
    const int grid = (B + TPB - 1) / TPB;
    grid_encode_kernel<<<grid, TPB>>>(inp, emb, tab, bnd, out, B);
}

// round 6
// speedup vs baseline: 2.1887x; 1.8107x over previous
#include <cuda_runtime.h>
#include <cuda_bf16.h>
#include <cstdint>

#define PRIME1 2654435761u
#define PRIME2 805459861u
#define HMASK  0x7FFFFu

#define TPB 256
#define PITCH 36   // mult of 4 (aligned float4 reads); 8-thread LDS.128 phases conflict-free

// Issue all 8 corner gathers for one level. Key trick: x-adjacent corner pairs
// are CONSECUTIVE table entries (dense: always; hashed: when ix is even, since
// ix+1 = ix^1 and xor/mask preserve the LSB flip -> pair {2k,2k+1}). An even
// pair start is a 16B-aligned float4: one LDG.128 (1 wavefront) replaces two
// random LDG.64s (2 wavefronts).
template<int LVL>
__device__ __forceinline__ void issue_level(
    float x, float y, float z,
    const float2* __restrict__ emb, const float2* __restrict__ tab,
    float& fx, float& fy, float& fz, float2* dst)
{
    const float scale = (float)(16 << LVL) - 1.0f;
    const float px = fmaf(x, scale, 0.5f);
    const float py = fmaf(y, scale, 0.5f);
    const float pz = fmaf(z, scale, 0.5f);
    const float fxf = floorf(px), fyf = floorf(py), fzf = floorf(pz);
    fx = px - fxf; fy = py - fyf; fz = pz - fzf;
    const unsigned ix = (unsigned)fxf, iy = (unsigned)fyf, iz = (unsigned)fzf;

    if (LVL <= 2) {
        const unsigned s  = (LVL == 0) ? 17u : (LVL == 1) ? 33u : 65u;
        const unsigned s2 = s * s;
        const unsigned off = (LVL == 2) ? 35944u : 0u;
        const float2* base = (LVL == 0) ? emb : tab;
        const unsigned id = ix + iy * s + iz * s2 + off;
        const unsigned starts[4] = {id, id + s, id + s2, id + s2 + s};
        #pragma unroll
        for (int p = 0; p < 4; p++) {
            const unsigned j = starts[p];
            if (!(j & 1u)) {
                const float4 v = __ldg((const float4*)(base + j));
                dst[2*p]   = make_float2(v.x, v.y);
                dst[2*p+1] = make_float2(v.z, v.w);
            } else {
                dst[2*p]   = __ldg(base + j);
                dst[2*p+1] = __ldg(base + j + 1);
            }
        }
    } else {
        const unsigned off = 310576u + (unsigned)(LVL - 3) * 524288u;
        const unsigned hy0 = iy * PRIME1, hy1 = hy0 + PRIME1;
        const unsigned hz0 = iz * PRIME2, hz1 = hz0 + PRIME2;
        const unsigned h0 = hy0 ^ hz0, h1 = hy1 ^ hz0, h2 = hy0 ^ hz1, h3 = hy1 ^ hz1;
        const unsigned hh[4] = {h0, h1, h2, h3};
        if (!(ix & 1u)) {
            // ix even: idx(ix+1) = idx(ix) ^ 1 -> pair {2k,2k+1}, one float4
            #pragma unroll
            for (int p = 0; p < 4; p++) {
                const unsigned j0 = (ix ^ hh[p]) & HMASK;
                const float4 v = __ldcg((const float4*)(tab + ((j0 & ~1u) + off)));
                const bool first = !(j0 & 1u);   // does ix's entry come first?
                dst[2*p].x   = first ? v.x : v.z;
                dst[2*p].y   = first ? v.y : v.w;
                dst[2*p+1].x = first ? v.z : v.x;
                dst[2*p+1].y = first ? v.w : v.y;
            }
        } else {
            #pragma unroll
            for (int p = 0; p < 4; p++) {
                dst[2*p]   = __ldcg(tab + (((ix      ) ^ hh[p]) & HMASK) + off);
                dst[2*p+1] = __ldcg(tab + (((ix + 1u) ^ hh[p]) & HMASK) + off);
            }
        }
    }
}

__global__ void __launch_bounds__(TPB, 5)
grid_encode_kernel(const float* __restrict__ inp,
                   const float2* __restrict__ emb,    // level 0 (4920 rows)
                   const float2* __restrict__ tab,    // levels 1..15
                   const int* __restrict__ boundp,
                   float* __restrict__ out,
                   int B)
{
    __shared__ float s_out[TPB * PITCH];

    const int tid = threadIdx.x;
    const long long b = (long long)blockIdx.x * TPB + tid;
    const bool valid = (b < B);

    float bnd = 1.0f;
    if (boundp) {
        int raw = __ldg(boundp);
        bnd = (raw > 0 && raw < 0x00800000) ? (float)raw : __int_as_float(raw);
    }
    const float inv = 0.5f / bnd;

    float x = 0.f, y = 0.f, z = 0.f;
    if (valid) {
        const float* p = inp + b * 3;
        x = __ldcs(p + 0); y = __ldcs(p + 1); z = __ldcs(p + 2);
    }
    x = fmaf(x, inv, 0.5f);
    y = fmaf(y, inv, 0.5f);
    z = fmaf(z, inv, 0.5f);

    if (valid) {
        // 2-stage software pipeline: level l+1's gathers issued before level
        // l's results are consumed -> ~16 loads in flight per warp.
        float cfx, cfy, cfz;
        float2 cur[8];
        issue_level<0>(x, y, z, emb, tab, cfx, cfy, cfz, cur);

        #define CONSUME(L)                                                         \
        {                                                                          \
            const float gx = 1.0f - cfx, gy = 1.0f - cfy, gz = 1.0f - cfz;         \
            const float w00 = gx * gy, w10 = cfx * gy, w01 = gx * cfy, w11 = cfx * cfy; \
            const float wa = w00 * gz, wb = w10 * gz, wc = w01 * gz, wd = w11 * gz;\
            const float we = w00 * cfz, wf = w10 * cfz, wg = w01 * cfz, wh = w11 * cfz; \
            float r0 = wa * cur[0].x,          r1 = wa * cur[0].y;                 \
            r0 = fmaf(wb, cur[1].x, r0);       r1 = fmaf(wb, cur[1].y, r1);        \
            r0 = fmaf(wc, cur[2].x, r0);       r1 = fmaf(wc, cur[2].y, r1);        \
            r0 = fmaf(wd, cur[3].x, r0);       r1 = fmaf(wd, cur[3].y, r1);        \
            r0 = fmaf(we, cur[4].x, r0);       r1 = fmaf(we, cur[4].y, r1);        \
            r0 = fmaf(wf, cur[5].x, r0);       r1 = fmaf(wf, cur[5].y, r1);        \
            r0 = fmaf(wg, cur[6].x, r0);       r1 = fmaf(wg, cur[6].y, r1);        \
            r0 = fmaf(wh, cur[7].x, r0);       r1 = fmaf(wh, cur[7].y, r1);        \
            *(float2*)&s_out[tid * PITCH + 2 * (L)] = make_float2(r0, r1);         \
        }

        #define STEP(L)                                                            \
        {                                                                          \
            float nfx, nfy, nfz;                                                   \
            float2 nxt[8];                                                         \
            issue_level<(L) + 1>(x, y, z, emb, tab, nfx, nfy, nfz, nxt);           \
            CONSUME(L)                                                             \
            cfx = nfx; cfy = nfy; cfz = nfz;                                       \
            _Pragma("unroll")                                                      \
            for (int c = 0; c < 8; c++) cur[c] = nxt[c];                           \
        }

        STEP(0)  STEP(1)  STEP(2)  STEP(3)
        STEP(4)  STEP(5)  STEP(6)  STEP(7)
        STEP(8)  STEP(9)  STEP(10) STEP(11)
        STEP(12) STEP(13) STEP(14)
        CONSUME(15)

        #undef STEP
        #undef CONSUME
    }

    __syncthreads();

    // Coalesced float4 writeback, evict-first so the 256MB output stream
    // doesn't flush the 57MB table out of L2.
    const long long blockBase = (long long)blockIdx.x * (TPB * 32);
#pragma unroll
    for (int j = 0; j < 8; j++) {
        const int f4 = tid + j * TPB;
        const int fl = f4 * 4;
        const int p  = fl >> 5;
        const int k  = fl & 31;
        const long long gp = (long long)blockIdx.x * TPB + p;
        if (gp < B) {
            const float4 v = *(const float4*)&s_out[p * PITCH + k];
            __stcs((float4*)&out[blockBase + fl], v);
        }
    }
}

extern "C" void kernel_launch(void* const* d_in, const int* in_sizes, int n_in,
                              void* d_out, int out_size)
{
    const float*  inp = (const float*)d_in[0];
    const float2* emb = (const float2*)d_in[1];
    const float2* tab = (const float2*)d_in[2];
    const int*    bnd = (n_in >= 4) ? (const int*)d_in[3] : nullptr;
    float* out = (float*)d_out;

    const int B = in_sizes[0] / 3;
    const int grid = (B + TPB - 1) / TPB;
    grid_encode_kernel<<<grid, TPB>>>(inp, emb, tab, bnd, out, B);
}